// round 5
// baseline (speedup 1.0000x reference)
#include <cuda_runtime.h>
#include <cstdint>

// Fixed problem shape: (N,C,H,W,T) = (8,16,32,32,500)
constexpr int N_ = 8;
constexpr int C_ = 16;
constexpr int H_ = 32;
constexpr int W_ = 32;
constexpr int T_ = 500;
constexpr int CHW = C_ * H_ * W_;     // 16384 (power of two)
constexpr int TV  = T_ / 4;           // 125 float4 per row
constexpr int NPER = 4;               // batch rows per thread
constexpr long long ROWSTRIDE = (long long)CHW * TV;  // float4 stride between n's

__device__ __forceinline__ float4 ldcs4(const float4* p) {
    // Streaming (evict-first) 128-bit load: keeps input out of L2 so the
    // output write stream owns the cache.
    float4 v;
    asm volatile("ld.global.cs.v4.f32 {%0,%1,%2,%3}, [%4];"
                 : "=f"(v.x), "=f"(v.y), "=f"(v.z), "=f"(v.w)
                 : "l"(p));
    return v;
}

__global__ void __launch_bounds__(256) delay_kernel(
    const float* __restrict__ x,
    const float* __restrict__ delay,
    const uint32_t* __restrict__ ts_bits,
    float* __restrict__ out)
{
    // blockIdx encodes (chw pair, n-half). 128 threads per chw.
    int tv  = threadIdx.x & 127;
    int chw = ((blockIdx.x >> 1) << 1) | (threadIdx.x >> 7);
    int n0  = (blockIdx.x & 1) * NPER;
    if (tv >= TV) return;

    // Decode Ts robustly (scalar may arrive as int32 or float32 bits).
    uint32_t tb = __ldg(ts_bits);
    float tf = __uint_as_float(tb);
    float Ts = (tf >= 1e-6f && tf <= 1e6f) ? tf : (float)(int)tb;

    // Per-chw shift parameters — shared by all n.
    float s    = __ldg(delay + chw) / Ts;
    float sif  = floorf(s);
    float frac = s - sif;
    int   si   = (int)sif;

    int start = -1 - si;         // first tap offset
    int q0 = start >> 2;         // floor-div-4
    int r  = start & 3;          // warp-uniform extract case

    int vi = tv + q0;
    bool va = (vi     >= 0) && (vi     < TV);
    bool vb = (vi + 1 >= 0) && (vi + 1 < TV);

    const float4* __restrict__ x4 = reinterpret_cast<const float4*>(x);
    const float4* basep = x4 + (long long)(n0 * CHW + chw) * TV + vi;

    // Front-batched independent streaming loads (8 x LDG.128.CS in flight).
    float4 z = make_float4(0.f, 0.f, 0.f, 0.f);
    float4 A[NPER], B[NPER];
#pragma unroll
    for (int j = 0; j < NPER; ++j) {
        A[j] = va ? ldcs4(basep + j * ROWSTRIDE)     : z;
        B[j] = vb ? ldcs4(basep + j * ROWSTRIDE + 1) : z;
    }

    float w1 = frac;
    float w0 = 1.0f - frac;
    float4* __restrict__ o4 =
        reinterpret_cast<float4*>(out) + (long long)(n0 * CHW + chw) * TV + tv;

#pragma unroll
    for (int j = 0; j < NPER; ++j) {
        float l0, l1, l2, l3, l4;
        switch (r) {
            case 0: l0 = A[j].x; l1 = A[j].y; l2 = A[j].z; l3 = A[j].w; l4 = B[j].x; break;
            case 1: l0 = A[j].y; l1 = A[j].z; l2 = A[j].w; l3 = B[j].x; l4 = B[j].y; break;
            case 2: l0 = A[j].z; l1 = A[j].w; l2 = B[j].x; l3 = B[j].y; l4 = B[j].z; break;
            default:l0 = A[j].w; l1 = B[j].x; l2 = B[j].y; l3 = B[j].z; l4 = B[j].w; break;
        }
        float4 o;
        o.x = w0 * l1 + w1 * l0;
        o.y = w0 * l2 + w1 * l1;
        o.z = w0 * l3 + w1 * l2;
        o.w = w0 * l4 + w1 * l3;
        o4[j * ROWSTRIDE] = o;
    }
}

extern "C" void kernel_launch(void* const* d_in, const int* in_sizes, int n_in,
                              void* d_out, int out_size)
{
    const float*    x     = (const float*)d_in[0];
    const float*    delay = (const float*)d_in[1];
    const uint32_t* ts    = (const uint32_t*)d_in[2];
    float*          out   = (float*)d_out;

    // CHW blocks: each covers 2 chw values x one n-half (4 rows per thread).
    delay_kernel<<<CHW, 256>>>(x, delay, ts, out);
}

// round 6
// speedup vs baseline: 1.0451x; 1.0451x over previous
#include <cuda_runtime.h>
#include <cstdint>

// Fixed problem shape: (N,C,H,W,T) = (8,16,32,32,500)
constexpr int N_ = 8;
constexpr int C_ = 16;
constexpr int H_ = 32;
constexpr int W_ = 32;
constexpr int T_ = 500;
constexpr int CHW = C_ * H_ * W_;     // 16384 (power of two)
constexpr int TV  = T_ / 4;           // 125 float4 per row
constexpr int NPER = 4;               // batch rows per thread
constexpr int ROWSTRIDE = CHW * TV;   // 2,048,000 float4 stride between n's (32-bit safe)

__global__ void __launch_bounds__(256, 6) delay_kernel(
    const float* __restrict__ x,
    const float* __restrict__ delay,
    const uint32_t* __restrict__ ts_bits,
    float* __restrict__ out)
{
    // blockIdx encodes (chw pair, n-half). 128 threads per chw.
    int tv  = threadIdx.x & 127;
    int chw = ((blockIdx.x >> 1) << 1) | (threadIdx.x >> 7);
    int n0  = (blockIdx.x & 1) * NPER;
    if (tv >= TV) return;

    // Decode Ts robustly (scalar may arrive as int32 or float32 bits).
    uint32_t tb = __ldg(ts_bits);
    float tf = __uint_as_float(tb);
    float Ts = (tf >= 1e-6f && tf <= 1e6f) ? tf : (float)(int)tb;

    // Per-chw shift parameters — shared by all n.
    float s    = __ldg(delay + chw) / Ts;
    float sif  = floorf(s);
    float frac = s - sif;
    int   si   = (int)sif;

    int start = -1 - si;         // first tap offset
    int q0 = start >> 2;         // floor-div-4
    int r  = start & 3;          // warp-uniform extract case

    int vi = tv + q0;
    bool va = (vi     >= 0) && (vi     < TV);
    bool vb = (vi + 1 >= 0) && (vi + 1 < TV);

    // Pure 32-bit indexing: total float4 count = 16.384M << 2^31.
    const float4* __restrict__ x4 = reinterpret_cast<const float4*>(x);
    int abase = (n0 * CHW + chw) * TV + vi;

    // Front-batched independent loads: 8 x LDG.128 in flight (MLP_p1 = 8).
    float4 z = make_float4(0.f, 0.f, 0.f, 0.f);
    float4 A[NPER], B[NPER];
#pragma unroll
    for (int j = 0; j < NPER; ++j) {
        A[j] = va ? __ldg(x4 + (abase + j * ROWSTRIDE))     : z;
        B[j] = vb ? __ldg(x4 + (abase + j * ROWSTRIDE + 1)) : z;
    }

    float w1 = frac;
    float w0 = 1.0f - frac;
    float4* __restrict__ o4 = reinterpret_cast<float4*>(out);
    int obase = (n0 * CHW + chw) * TV + tv;

#pragma unroll
    for (int j = 0; j < NPER; ++j) {
        float l0, l1, l2, l3, l4;
        switch (r) {
            case 0: l0 = A[j].x; l1 = A[j].y; l2 = A[j].z; l3 = A[j].w; l4 = B[j].x; break;
            case 1: l0 = A[j].y; l1 = A[j].z; l2 = A[j].w; l3 = B[j].x; l4 = B[j].y; break;
            case 2: l0 = A[j].z; l1 = A[j].w; l2 = B[j].x; l3 = B[j].y; l4 = B[j].z; break;
            default:l0 = A[j].w; l1 = B[j].x; l2 = B[j].y; l3 = B[j].z; l4 = B[j].w; break;
        }
        float4 o;
        o.x = w0 * l1 + w1 * l0;
        o.y = w0 * l2 + w1 * l1;
        o.z = w0 * l3 + w1 * l2;
        o.w = w0 * l4 + w1 * l3;
        o4[obase + j * ROWSTRIDE] = o;
    }
}

extern "C" void kernel_launch(void* const* d_in, const int* in_sizes, int n_in,
                              void* d_out, int out_size)
{
    const float*    x     = (const float*)d_in[0];
    const float*    delay = (const float*)d_in[1];
    const uint32_t* ts    = (const uint32_t*)d_in[2];
    float*          out   = (float*)d_out;

    // CHW blocks: each covers 2 chw values x one n-half (4 rows per thread).
    delay_kernel<<<CHW, 256>>>(x, delay, ts, out);
}

// round 7
// speedup vs baseline: 1.0501x; 1.0048x over previous
#include <cuda_runtime.h>
#include <cstdint>

// Fixed problem shape: (N,C,H,W,T) = (8,16,32,32,500)
constexpr int N_ = 8;
constexpr int C_ = 16;
constexpr int H_ = 32;
constexpr int W_ = 32;
constexpr int T_ = 500;
constexpr int CHW = C_ * H_ * W_;     // 16384 (power of two)
constexpr int TV  = T_ / 4;           // 125 float4 per row
constexpr int NPER = 4;               // batch rows per thread
constexpr int ROWSTRIDE = CHW * TV;   // float4 stride between n's (32-bit safe)

__global__ void __launch_bounds__(256, 7) delay_kernel(
    const float* __restrict__ x,
    const float* __restrict__ delay,
    const uint32_t* __restrict__ ts_bits,
    float* __restrict__ out)
{
    // blockIdx encodes (chw pair, n-half). 128 threads per chw.
    int tv   = threadIdx.x & 127;
    int chw  = ((blockIdx.x >> 1) << 1) | (threadIdx.x >> 7);
    int n0   = (blockIdx.x & 1) * NPER;
    int lane = threadIdx.x & 31;
    bool active = tv < TV;            // tv 125..127 stay alive for shfl

    // Decode Ts robustly (scalar may arrive as int32 or float32 bits).
    uint32_t tb = __ldg(ts_bits);
    float tf = __uint_as_float(tb);
    float Ts = (tf >= 1e-6f && tf <= 1e6f) ? tf : (float)(int)tb;

    // Per-chw shift parameters — shared by all n.
    float s    = __ldg(delay + chw) / Ts;
    float sif  = floorf(s);
    float frac = s - sif;
    int   si   = (int)sif;

    int start = -1 - si;         // first tap offset
    int q0 = start >> 2;         // floor-div-4
    int r  = start & 3;          // warp-uniform extract case

    const float4* __restrict__ x4 = reinterpret_cast<const float4*>(x);
    float4* __restrict__ o4 = reinterpret_cast<float4*>(out);
    int obase = (n0 * CHW + chw) * TV + tv;

    float w1 = frac;
    float w0 = 1.0f - frac;
    float4 z = make_float4(0.f, 0.f, 0.f, 0.f);

    if (r == 3) {
        // HOT PATH (true whenever start % 4 == 3; always true for delay in [0,1)):
        // taps = { V[wv-1].w, V[wv].x, V[wv].y, V[wv].z, V[wv].w }, wv = tv+q0+1.
        // One LDG.128 per (j, thread); cross-vector tap via shfl_up; lane 0
        // patches with one predicated scalar load.
        int wv = tv + q0 + 1;
        bool vw = (wv >= 0) && (wv < TV);          // V[wv] element-exact validity
        bool vn = (wv >= 1) && (wv <= TV);         // element 4*wv-1 validity
        bool le = (lane == 0);

        int abase = (n0 * CHW + chw) * TV + wv;

        float4 Wv[NPER];
        float  Ew[NPER];
#pragma unroll
        for (int j = 0; j < NPER; ++j) {
            Wv[j] = vw ? __ldg(x4 + abase + j * ROWSTRIDE) : z;
            Ew[j] = (le && vn) ? __ldg(x + ((abase + j * ROWSTRIDE) << 2) - 1) : 0.0f;
        }

#pragma unroll
        for (int j = 0; j < NPER; ++j) {
            float nbw = __shfl_up_sync(0xffffffffu, Wv[j].w, 1);
            if (lane == 0) nbw = Ew[j];
            float4 o;
            o.x = w0 * Wv[j].x + w1 * nbw;
            o.y = w0 * Wv[j].y + w1 * Wv[j].x;
            o.z = w0 * Wv[j].z + w1 * Wv[j].y;
            o.w = w0 * Wv[j].w + w1 * Wv[j].z;
            if (active) o4[obase + j * ROWSTRIDE] = o;
        }
    } else {
        // FALLBACK (warp-uniform, never taken for this dataset): two vector
        // loads per (j, thread), general r extraction. Identical to R6 path.
        if (!active) return;
        int vi = tv + q0;
        bool va = (vi     >= 0) && (vi     < TV);
        bool vb = (vi + 1 >= 0) && (vi + 1 < TV);
        int abase = (n0 * CHW + chw) * TV + vi;

        float4 A[NPER], B[NPER];
#pragma unroll
        for (int j = 0; j < NPER; ++j) {
            A[j] = va ? __ldg(x4 + abase + j * ROWSTRIDE)     : z;
            B[j] = vb ? __ldg(x4 + abase + j * ROWSTRIDE + 1) : z;
        }
#pragma unroll
        for (int j = 0; j < NPER; ++j) {
            float l0, l1, l2, l3, l4;
            switch (r) {
                case 0: l0 = A[j].x; l1 = A[j].y; l2 = A[j].z; l3 = A[j].w; l4 = B[j].x; break;
                case 1: l0 = A[j].y; l1 = A[j].z; l2 = A[j].w; l3 = B[j].x; l4 = B[j].y; break;
                default:l0 = A[j].z; l1 = A[j].w; l2 = B[j].x; l3 = B[j].y; l4 = B[j].z; break;
            }
            float4 o;
            o.x = w0 * l1 + w1 * l0;
            o.y = w0 * l2 + w1 * l1;
            o.z = w0 * l3 + w1 * l2;
            o.w = w0 * l4 + w1 * l3;
            o4[obase + j * ROWSTRIDE] = o;
        }
    }
}

extern "C" void kernel_launch(void* const* d_in, const int* in_sizes, int n_in,
                              void* d_out, int out_size)
{
    const float*    x     = (const float*)d_in[0];
    const float*    delay = (const float*)d_in[1];
    const uint32_t* ts    = (const uint32_t*)d_in[2];
    float*          out   = (float*)d_out;

    // CHW blocks: each covers 2 chw values x one n-half (4 rows per thread).
    delay_kernel<<<CHW, 256>>>(x, delay, ts, out);
}